// round 1
// baseline (speedup 1.0000x reference)
#include <cuda_runtime.h>
#include <math.h>

#define NNC 256          // node feature dim C
#define NNB 512          // number of graphs B
#define NSTEPS 3

// ---------------- device scratch (no allocations allowed) ----------------
__device__ float g_hA[NNB * NNC];
__device__ float g_hB[NNB * NNC];
__device__ float g_c[NNB * NNC];
__device__ float g_qstar[NNB * 2 * NNC];
__device__ int   g_segstart[NNB + 1];
__device__ int   g_is64;

// ---------------- dtype detection for `batch` (int32 vs int64) ----------------
// If batch is stored as int64 (little-endian, values < 2^31), every odd 32-bit
// word within the first N words is a zero high-half. If it is int32, odd words
// are real batch values (sorted up to B-1 -> plenty nonzero).
__global__ void detect_kernel(const unsigned int* __restrict__ raw, int nwords) {
    __shared__ int found;
    if (threadIdx.x == 0) found = 0;
    __syncthreads();
    int any = 0;
    for (int i = 2 * threadIdx.x + 1; i < nwords; i += 2 * blockDim.x) {
        if (raw[i] != 0u) { any = 1; break; }
    }
    if (any) atomicExch(&found, 1);
    __syncthreads();
    if (threadIdx.x == 0) g_is64 = (found == 0) ? 1 : 0;
}

__device__ __forceinline__ int seg_of(const void* braw, int i) {
    if (g_is64) return (int)(((const long long*)braw)[i]);
    return ((const int*)braw)[i];
}

// ---------------- init ----------------
__global__ void zero_kernel() {
    int i = blockIdx.x * blockDim.x + threadIdx.x;
    int stride = gridDim.x * blockDim.x;
    for (int k = i; k < NNB * NNC; k += stride) { g_hA[k] = 0.f; g_c[k] = 0.f; }
    for (int k = i; k < NNB * 2 * NNC; k += stride) g_qstar[k] = 0.f;
}

// segment start offsets from the sorted batch array; g_segstart[B] = N sentinel
__global__ void segstart_kernel(const void* __restrict__ braw, int n) {
    int i = blockIdx.x * blockDim.x + threadIdx.x;
    if (i > n) return;
    int cur  = (i == n) ? NNB : seg_of(braw, i);
    if (cur > NNB) cur = NNB;
    int prev = (i == 0) ? -1 : seg_of(braw, i - 1);
    for (int b = prev + 1; b <= cur; b++) {
        g_segstart[b] = i;
    }
}

// ---------------- fused LSTM cell ----------------
// gates[b, 4C] = concat(q_star[b,:512], h_in[b,:256]) @ W^T + b_ih + b_hh
// then c_new = sig(f)*c + sig(i)*tanh(g); h_new = sig(o)*tanh(c_new)
// Tiling: block = 32 b-rows x 32 c-cols x 4 gates, 256 threads, K staged by 32.
__global__ void __launch_bounds__(256) lstm_kernel(
    const float* __restrict__ W_ih, const float* __restrict__ W_hh,
    const float* __restrict__ b_ih, const float* __restrict__ b_hh,
    int flip)
{
    const float* h_in = flip ? g_hB : g_hA;
    float* h_out      = flip ? g_hA : g_hB;

    __shared__ float sA[32][32];        // A rows (b) x k
    __shared__ float sW[4][32][33];     // gate x k x c (padded: conflict-free)

    int c0 = blockIdx.x * 32;           // 8 c-tiles
    int b0 = blockIdx.y * 32;           // 16 b-tiles
    int tid = threadIdx.x;
    int tx = tid & 31;                  // c within tile
    int ty = tid >> 5;                  // 0..7 -> rows ty*4 .. ty*4+3

    float acc[4][4];
    #pragma unroll
    for (int r = 0; r < 4; r++)
        #pragma unroll
        for (int g = 0; g < 4; g++) acc[r][g] = 0.f;

    for (int k0 = 0; k0 < 768; k0 += 32) {
        const float* Asrc; int pitch, col;
        if (k0 < 512) { Asrc = g_qstar; pitch = 512; col = k0; }
        else          { Asrc = h_in;    pitch = 256; col = k0 - 512; }

        // stage A tile: 32x32 (coalesced: warp reads 32 consecutive floats)
        #pragma unroll
        for (int t = 0; t < 4; t++) {
            int idx = tid + t * 256;
            int r = idx >> 5, kk = idx & 31;
            sA[r][kk] = Asrc[(b0 + r) * pitch + col + kk];
        }
        // stage W tile: 4 gates x 32 c x 32 k, stored transposed [g][k][c]
        #pragma unroll
        for (int t = 0; t < 16; t++) {
            int idx = tid + t * 256;
            int g  = idx >> 10;
            int cc = (idx >> 5) & 31;
            int kk = idx & 31;
            int row = g * 256 + c0 + cc;
            float v;
            if (k0 < 512) v = W_ih[row * 512 + k0 + kk];
            else          v = W_hh[row * 256 + (k0 - 512) + kk];
            sW[g][kk][cc] = v;
        }
        __syncthreads();

        #pragma unroll 8
        for (int kk = 0; kk < 32; kk++) {
            float a0 = sA[ty * 4 + 0][kk];
            float a1 = sA[ty * 4 + 1][kk];
            float a2 = sA[ty * 4 + 2][kk];
            float a3 = sA[ty * 4 + 3][kk];
            float w0 = sW[0][kk][tx];
            float w1 = sW[1][kk][tx];
            float w2 = sW[2][kk][tx];
            float w3 = sW[3][kk][tx];
            acc[0][0] += a0 * w0; acc[0][1] += a0 * w1; acc[0][2] += a0 * w2; acc[0][3] += a0 * w3;
            acc[1][0] += a1 * w0; acc[1][1] += a1 * w1; acc[1][2] += a1 * w2; acc[1][3] += a1 * w3;
            acc[2][0] += a2 * w0; acc[2][1] += a2 * w1; acc[2][2] += a2 * w2; acc[2][3] += a2 * w3;
            acc[3][0] += a3 * w0; acc[3][1] += a3 * w1; acc[3][2] += a3 * w2; acc[3][3] += a3 * w3;
        }
        __syncthreads();
    }

    int c = c0 + tx;
    float bi = b_ih[c]           + b_hh[c];
    float bf = b_ih[256 + c]     + b_hh[256 + c];
    float bg = b_ih[512 + c]     + b_hh[512 + c];
    float bo = b_ih[768 + c]     + b_hh[768 + c];

    #pragma unroll
    for (int r = 0; r < 4; r++) {
        int b = b0 + ty * 4 + r;
        float gi = acc[r][0] + bi;
        float gf = acc[r][1] + bf;
        float gg = acc[r][2] + bg;
        float go = acc[r][3] + bo;
        float si = 1.f / (1.f + __expf(-gi));
        float sf = 1.f / (1.f + __expf(-gf));
        float so = 1.f / (1.f + __expf(-go));
        float tg = tanhf(gg);
        float cn = sf * g_c[b * 256 + c] + si * tg;   // unique (b,c) per thread: in-place safe
        float hn = so * tanhf(cn);
        g_c[b * 256 + c]  = cn;
        h_out[b * 256 + c] = hn;
    }
}

// ---------------- fused segment-softmax attention (single pass over x) ----------------
// One block per graph b. 16 warps; warp w processes nodes s+w, s+w+16, ...
// Lane l owns x columns [8l, 8l+8). Online softmax with register accumulator:
// x row is loaded ONCE and used for both e_i = x_i . q and the weighted sum.
__global__ void __launch_bounds__(512) attn_kernel(const float* __restrict__ x, int flip) {
    const float* q_src = flip ? g_hA : g_hB;   // h_out of this step

    int b = blockIdx.x;
    int s = g_segstart[b];
    int e = g_segstart[b + 1];
    int tid  = threadIdx.x;
    int lane = tid & 31;
    int w    = tid >> 5;

    __shared__ float sm_m[16];
    __shared__ float sm_Z[16];
    __shared__ float sm_acc[16 * 256];

    // q slice for this lane
    const float4* qp = (const float4*)(q_src + b * 256 + lane * 8);
    float4 q0 = __ldg(qp);
    float4 q1 = __ldg(qp + 1);

    float m = -1e30f, Z = 0.f;
    float a0 = 0.f, a1 = 0.f, a2 = 0.f, a3 = 0.f, a4 = 0.f, a5 = 0.f, a6 = 0.f, a7 = 0.f;

    int i = s + w;
    float4 cx0 = make_float4(0.f, 0.f, 0.f, 0.f), cx1 = cx0, nx0 = cx0, nx1 = cx0;
    if (i < e) {
        const float4* p = (const float4*)(x + (size_t)i * 256 + lane * 8);
        cx0 = __ldg(p); cx1 = __ldg(p + 1);
    }
    while (i < e) {
        int inext = i + 16;
        if (inext < e) {  // prefetch next row while computing current
            const float4* p = (const float4*)(x + (size_t)inext * 256 + lane * 8);
            nx0 = __ldg(p); nx1 = __ldg(p + 1);
        }
        float d = cx0.x * q0.x + cx0.y * q0.y + cx0.z * q0.z + cx0.w * q0.w
                + cx1.x * q1.x + cx1.y * q1.y + cx1.z * q1.z + cx1.w * q1.w;
        #pragma unroll
        for (int o = 16; o > 0; o >>= 1) d += __shfl_xor_sync(0xffffffffu, d, o);

        float mn = fmaxf(m, d);
        float sc = __expf(m - mn);     // underflows to 0 on first node
        float p  = __expf(d - mn);
        Z = Z * sc + p;
        a0 = a0 * sc + p * cx0.x;
        a1 = a1 * sc + p * cx0.y;
        a2 = a2 * sc + p * cx0.z;
        a3 = a3 * sc + p * cx0.w;
        a4 = a4 * sc + p * cx1.x;
        a5 = a5 * sc + p * cx1.y;
        a6 = a6 * sc + p * cx1.z;
        a7 = a7 * sc + p * cx1.w;
        m = mn;

        cx0 = nx0; cx1 = nx1;
        i = inext;
    }

    // stash per-warp partials
    float4* ap = (float4*)&sm_acc[w * 256 + lane * 8];
    ap[0] = make_float4(a0, a1, a2, a3);
    ap[1] = make_float4(a4, a5, a6, a7);
    if (lane == 0) { sm_m[w] = m; sm_Z[w] = Z; }
    __syncthreads();

    if (tid < 256) {
        float M = -1e30f;
        #pragma unroll
        for (int ww = 0; ww < 16; ww++) M = fmaxf(M, sm_m[ww]);
        float r = 0.f;
        if (M > -1e29f) {              // non-empty segment
            float Zt = 0.f;
            #pragma unroll
            for (int ww = 0; ww < 16; ww++) {
                float sc = __expf(sm_m[ww] - M);
                Zt += sc * sm_Z[ww];
                r  += sc * sm_acc[ww * 256 + tid];
            }
            r = r / Zt;
        }
        g_qstar[b * 512 + 256 + tid] = r;                 // r half
        g_qstar[b * 512 + tid] = q_src[b * 256 + tid];    // q half (for next step / output)
    }
}

__global__ void copy_out_kernel(float* __restrict__ out) {
    int i = blockIdx.x * blockDim.x + threadIdx.x;
    if (i < NNB * 2 * NNC) out[i] = g_qstar[i];
}

// ---------------- launcher ----------------
extern "C" void kernel_launch(void* const* d_in, const int* in_sizes, int n_in,
                              void* d_out, int out_size) {
    const float* x     = (const float*)d_in[0];
    const void*  batch = d_in[1];
    const float* W_ih  = (const float*)d_in[2];
    const float* W_hh  = (const float*)d_in[3];
    const float* b_ih  = (const float*)d_in[4];
    const float* b_hh  = (const float*)d_in[5];
    int n = in_sizes[1];   // number of nodes

    detect_kernel<<<1, 256>>>((const unsigned int*)batch, n);
    zero_kernel<<<256, 256>>>();
    segstart_kernel<<<(n + 256) / 256, 256>>>(batch, n);

    for (int s = 0; s < NSTEPS; s++) {
        int flip = s & 1;
        dim3 lgrid(8, 16);   // (c tiles, b tiles)
        lstm_kernel<<<lgrid, 256>>>(W_ih, W_hh, b_ih, b_hh, flip);
        attn_kernel<<<NNB, 512>>>(x, flip);
    }
    copy_out_kernel<<<(NNB * 2 * NNC + 255) / 256, 256>>>((float*)d_out);
}

// round 2
// speedup vs baseline: 1.4569x; 1.4569x over previous
#include <cuda_runtime.h>
#include <math.h>

#define NNC 256          // node feature dim C
#define NNB 512          // number of graphs B
#define NSTEPS 3

// ---------------- device scratch (no allocations allowed) ----------------
__device__ float g_bufA[NNB * 512];     // q_star ping
__device__ float g_bufB[NNB * 512];     // q_star pong
__device__ float g_c[NNB * NNC];        // LSTM cell state
__device__ float g_Wt[512 * 1024];      // folded weight, [k][n'], n' = c*4 + gate
__device__ float g_bias[1024];          // folded bias in n' layout
__device__ int   g_segstart[NNB + 1];
__device__ int   g_is64;

// ---------------- init: zero state, preset dtype flag ----------------
__global__ void zero_kernel() {
    int i = blockIdx.x * blockDim.x + threadIdx.x;
    int stride = gridDim.x * blockDim.x;
    for (int k = i; k < NNB * 512; k += stride) g_bufA[k] = 0.f;
    for (int k = i; k < NNB * NNC; k += stride) g_c[k] = 0.f;
    if (i == 0) g_is64 = 1;
}

// ---------------- dtype detection for `batch` (int32 vs int64) ----------------
// int64 storage (values < 2^31): every odd 32-bit word is zero. int32: odd
// words are real (sorted) batch values, plenty nonzero. Benign racy store.
__global__ void detect_kernel(const unsigned int* __restrict__ raw, int nwords) {
    int i = 2 * (blockIdx.x * blockDim.x + threadIdx.x) + 1;
    int stride = 2 * gridDim.x * blockDim.x;
    for (; i < nwords; i += stride) {
        if (raw[i] != 0u) { g_is64 = 0; return; }
    }
}

__device__ __forceinline__ int seg_of(const void* braw, int i) {
    if (g_is64) return (int)(((const long long*)braw)[i]);
    return ((const int*)braw)[i];
}

// segment start offsets from the sorted batch array; g_segstart[B] = N sentinel
__global__ void segstart_kernel(const void* __restrict__ braw, int n) {
    int i = blockIdx.x * blockDim.x + threadIdx.x;
    if (i > n) return;
    int cur  = (i == n) ? NNB : seg_of(braw, i);
    if (cur > NNB) cur = NNB;
    int prev = (i == 0) ? -1 : seg_of(braw, i - 1);
    for (int b = prev + 1; b <= cur; b++) g_segstart[b] = i;
}

// ---------------- fold weights (once per launch) ----------------
// q_star[:, :256] == h identically, so fold W_hh into W_ih's first 256 cols.
// Store transposed + gate-interleaved: g_Wt[k*1024 + c*4 + g] = Wf[g*256+c][k]
__global__ void fold_kernel(const float* __restrict__ W_ih,
                            const float* __restrict__ W_hh,
                            const float* __restrict__ b_ih,
                            const float* __restrict__ b_hh) {
    int idx = blockIdx.x * blockDim.x + threadIdx.x;
    if (idx >= 512 * 1024) return;
    int np = idx & 1023;          // n' = c*4 + g
    int k  = idx >> 10;
    int g  = np & 3;
    int c  = np >> 2;
    int no = g * 256 + c;         // original gate-major row
    float v = W_ih[no * 512 + k];
    if (k < 256) v += W_hh[no * 256 + k];
    g_Wt[idx] = v;
    if (k == 0) g_bias[np] = b_ih[no] + b_hh[no];
}

// ---------------- fused LSTM: GEMM [512x1024x512] + gate activations ----------------
// A = prev q_star [512][512]. Block tile 64(M) x 64(N'), 256 threads, 4x4/thread,
// double-buffered smem, register-staged global prefetch. Because N' is
// gate-interleaved, each thread's 4 N-accumulators = (i,f,g,o) of one (b,c).
__global__ void __launch_bounds__(256, 1) gemm_lstm_kernel(
    const float* __restrict__ A, float* __restrict__ hout, float* __restrict__ out2)
{
    __shared__ float sA[2][16][68];   // [buf][k][m], pad 68 keeps float4-aligned rows
    __shared__ float sB[2][16][64];   // [buf][k][n']

    int tid = threadIdx.x;
    int tm = tid & 15;                // 16 m-subtiles of 4
    int tn = tid >> 4;                // 16 n-subtiles of 4
    int m0 = blockIdx.y * 64;
    int n0 = blockIdx.x * 64;

    // staging roles
    int am  = tid >> 2;               // 0..63 : m row
    int akq = tid & 3;                // 0..3  : k quad
    const float* aptr = A + (m0 + am) * 512 + akq * 4;
    int bk = tid >> 4;                // 0..15 : k row
    int bc = (tid & 15) * 4;          // col quad
    const float* bptr = g_Wt + bk * 1024 + n0 + bc;

    float4 ra = *(const float4*)aptr;
    float4 rb = *(const float4*)bptr;
    sA[0][akq * 4 + 0][am] = ra.x;
    sA[0][akq * 4 + 1][am] = ra.y;
    sA[0][akq * 4 + 2][am] = ra.z;
    sA[0][akq * 4 + 3][am] = ra.w;
    *(float4*)&sB[0][bk][bc] = rb;
    __syncthreads();

    float acc[4][4];
    #pragma unroll
    for (int r = 0; r < 4; r++)
        #pragma unroll
        for (int n = 0; n < 4; n++) acc[r][n] = 0.f;

    const int NK = 512 / 16;
    for (int kb = 0; kb < NK; kb++) {
        int cur = kb & 1;
        if (kb + 1 < NK) {
            ra = *(const float4*)(aptr + (kb + 1) * 16);
            rb = *(const float4*)(bptr + (size_t)(kb + 1) * 16 * 1024);
        }
        #pragma unroll
        for (int kk = 0; kk < 16; kk++) {
            float4 va = *(float4*)&sA[cur][kk][tm * 4];
            float4 vb = *(float4*)&sB[cur][kk][tn * 4];
            acc[0][0] += va.x * vb.x; acc[0][1] += va.x * vb.y; acc[0][2] += va.x * vb.z; acc[0][3] += va.x * vb.w;
            acc[1][0] += va.y * vb.x; acc[1][1] += va.y * vb.y; acc[1][2] += va.y * vb.z; acc[1][3] += va.y * vb.w;
            acc[2][0] += va.z * vb.x; acc[2][1] += va.z * vb.y; acc[2][2] += va.z * vb.z; acc[2][3] += va.z * vb.w;
            acc[3][0] += va.w * vb.x; acc[3][1] += va.w * vb.y; acc[3][2] += va.w * vb.z; acc[3][3] += va.w * vb.w;
        }
        if (kb + 1 < NK) {
            int nxt = cur ^ 1;
            sA[nxt][akq * 4 + 0][am] = ra.x;
            sA[nxt][akq * 4 + 1][am] = ra.y;
            sA[nxt][akq * 4 + 2][am] = ra.z;
            sA[nxt][akq * 4 + 3][am] = ra.w;
            *(float4*)&sB[nxt][bk][bc] = rb;
        }
        __syncthreads();
    }

    // fused LSTM pointwise epilogue: thread owns gates (i,f,g,o) of 4 (b,c) cells
    int c = (n0 >> 2) + tn;
    float4 bs = *(const float4*)&g_bias[n0 + tn * 4];
    #pragma unroll
    for (int mi = 0; mi < 4; mi++) {
        int b = m0 + tm * 4 + mi;
        float gi = acc[mi][0] + bs.x;
        float gf = acc[mi][1] + bs.y;
        float gg = acc[mi][2] + bs.z;
        float go = acc[mi][3] + bs.w;
        float si = 1.f / (1.f + __expf(-gi));
        float sf = 1.f / (1.f + __expf(-gf));
        float so = 1.f / (1.f + __expf(-go));
        float tg = tanhf(gg);
        float cn = sf * g_c[b * 256 + c] + si * tg;   // each (b,c) owned by one thread
        float hn = so * tanhf(cn);
        g_c[b * 256 + c] = cn;
        hout[b * 512 + c] = hn;
        if (out2) out2[b * 512 + c] = hn;
    }
}

// ---------------- fused segment-softmax attention (single pass over x) ----------------
// One block per graph. 16 warps stride the segment; lane owns 8 columns.
// Online softmax: each x row is read ONCE for both the logit and the weighted sum.
__global__ void __launch_bounds__(512) attn_kernel(
    const float* __restrict__ x, const float* __restrict__ qsrc,
    float* __restrict__ rdst, float* __restrict__ out2)
{
    int b = blockIdx.x;
    int s = g_segstart[b];
    int e = g_segstart[b + 1];
    int tid  = threadIdx.x;
    int lane = tid & 31;
    int w    = tid >> 5;

    __shared__ float sm_m[16];
    __shared__ float sm_Z[16];
    __shared__ float sm_acc[16 * 256];

    const float4* qp = (const float4*)(qsrc + b * 512 + lane * 8);
    float4 q0 = __ldg(qp);
    float4 q1 = __ldg(qp + 1);

    float m = -1e30f, Z = 0.f;
    float a0 = 0.f, a1 = 0.f, a2 = 0.f, a3 = 0.f, a4 = 0.f, a5 = 0.f, a6 = 0.f, a7 = 0.f;

    int i = s + w;
    float4 cx0 = make_float4(0.f, 0.f, 0.f, 0.f), cx1 = cx0, nx0 = cx0, nx1 = cx0;
    if (i < e) {
        const float4* p = (const float4*)(x + (size_t)i * 256 + lane * 8);
        cx0 = __ldg(p); cx1 = __ldg(p + 1);
    }
    while (i < e) {
        int inext = i + 16;
        if (inext < e) {
            const float4* p = (const float4*)(x + (size_t)inext * 256 + lane * 8);
            nx0 = __ldg(p); nx1 = __ldg(p + 1);
        }
        float d = cx0.x * q0.x + cx0.y * q0.y + cx0.z * q0.z + cx0.w * q0.w
                + cx1.x * q1.x + cx1.y * q1.y + cx1.z * q1.z + cx1.w * q1.w;
        #pragma unroll
        for (int o = 16; o > 0; o >>= 1) d += __shfl_xor_sync(0xffffffffu, d, o);

        float mn = fmaxf(m, d);
        float sc = __expf(m - mn);
        float p  = __expf(d - mn);
        Z = Z * sc + p;
        a0 = a0 * sc + p * cx0.x;
        a1 = a1 * sc + p * cx0.y;
        a2 = a2 * sc + p * cx0.z;
        a3 = a3 * sc + p * cx0.w;
        a4 = a4 * sc + p * cx1.x;
        a5 = a5 * sc + p * cx1.y;
        a6 = a6 * sc + p * cx1.z;
        a7 = a7 * sc + p * cx1.w;
        m = mn;

        cx0 = nx0; cx1 = nx1;
        i = inext;
    }

    float4* ap = (float4*)&sm_acc[w * 256 + lane * 8];
    ap[0] = make_float4(a0, a1, a2, a3);
    ap[1] = make_float4(a4, a5, a6, a7);
    if (lane == 0) { sm_m[w] = m; sm_Z[w] = Z; }
    __syncthreads();

    if (tid < 256) {
        float M = -1e30f;
        #pragma unroll
        for (int ww = 0; ww < 16; ww++) M = fmaxf(M, sm_m[ww]);
        float r = 0.f;
        if (M > -1e29f) {
            float Zt = 0.f;
            #pragma unroll
            for (int ww = 0; ww < 16; ww++) {
                float sc = __expf(sm_m[ww] - M);
                Zt += sc * sm_Z[ww];
                r  += sc * sm_acc[ww * 256 + tid];
            }
            r = r / Zt;
        }
        rdst[b * 512 + 256 + tid] = r;
        if (out2) out2[b * 512 + 256 + tid] = r;
    }
}

// ---------------- launcher ----------------
extern "C" void kernel_launch(void* const* d_in, const int* in_sizes, int n_in,
                              void* d_out, int out_size) {
    const float* x     = (const float*)d_in[0];
    const void*  batch = d_in[1];
    const float* W_ih  = (const float*)d_in[2];
    const float* W_hh  = (const float*)d_in[3];
    const float* b_ih  = (const float*)d_in[4];
    const float* b_hh  = (const float*)d_in[5];
    int n = in_sizes[1];

    zero_kernel<<<256, 256>>>();
    detect_kernel<<<128, 256>>>((const unsigned int*)batch, n);
    segstart_kernel<<<(n + 256) / 256, 256>>>(batch, n);
    fold_kernel<<<(512 * 1024 + 255) / 256, 256>>>(W_ih, W_hh, b_ih, b_hh);

    float* bufs[2] = { nullptr, nullptr };
    // resolve device-global addresses via symbols is not allowed inside graph-
    // capture-unfriendly APIs; use kernels taking raw pointers via cudaGetSymbolAddress
    void* pA; void* pB;
    cudaGetSymbolAddress(&pA, g_bufA);
    cudaGetSymbolAddress(&pB, g_bufB);
    bufs[0] = (float*)pA;
    bufs[1] = (float*)pB;

    for (int s = 0; s < NSTEPS; s++) {
        const float* src = bufs[s & 1];
        float*       dst = bufs[(s + 1) & 1];
        float* out2 = (s == NSTEPS - 1) ? (float*)d_out : nullptr;
        dim3 ggrid(16, 8);   // (n' tiles, m tiles)
        gemm_lstm_kernel<<<ggrid, 256>>>(src, dst, out2);
        attn_kernel<<<NNB, 512>>>(x, dst, dst, out2);
    }
}

// round 5
// speedup vs baseline: 1.6389x; 1.1249x over previous
#include <cuda_runtime.h>
#include <math.h>

#define NNC 256          // node feature dim C
#define NNB 512          // number of graphs B
#define NSTEPS 3

// ---------------- device scratch (no allocations allowed) ----------------
__device__ float g_bufA[NNB * 512];     // q_star ping
__device__ float g_bufB[NNB * 512];     // q_star pong
__device__ float g_c[NNB * NNC];        // LSTM cell state
__device__ float g_Wf[1024 * 512];      // folded weight, row-major [no][k] (no = g*256+c)
__device__ float g_bias[1024];          // folded bias, n' layout (n' = c*4 + g)
__device__ int   g_segstart[NNB + 1];
__device__ int   g_is64;

// ---------------- setup: fold W_hh into W_ih (coalesced), fold bias, init flag ----
__global__ void setup_kernel(const float* __restrict__ W_ih,
                             const float* __restrict__ W_hh,
                             const float* __restrict__ b_ih,
                             const float* __restrict__ b_hh) {
    int idx = blockIdx.x * blockDim.x + threadIdx.x;
    if (idx < 1024 * 512) {
        int k  = idx & 511;
        int no = idx >> 9;
        float v = W_ih[idx];
        if (k < 256) v += W_hh[no * 256 + k];
        g_Wf[idx] = v;
    }
    if (idx < 1024) {               // n' = c*4 + g
        int g = idx & 3, c = idx >> 2;
        int no = g * 256 + c;
        g_bias[idx] = b_ih[no] + b_hh[no];
    }
    if (idx == 0) g_is64 = 1;
}

// ---------------- dtype detection for `batch` (int32 vs int64) ----------------
// int64 storage (values < 2^31): every odd 32-bit word is zero. int32: odd
// words are real (sorted) batch values, plenty nonzero. Benign racy store.
__global__ void detect_kernel(const unsigned int* __restrict__ raw, int nwords) {
    int i = 2 * (blockIdx.x * blockDim.x + threadIdx.x) + 1;
    int stride = 2 * gridDim.x * blockDim.x;
    for (; i < nwords; i += stride) {
        if (raw[i] != 0u) { g_is64 = 0; return; }
    }
}

__device__ __forceinline__ int seg_of(const void* braw, int i) {
    if (g_is64) return (int)(((const long long*)braw)[i]);
    return ((const int*)braw)[i];
}

// segment start offsets from the sorted batch array; g_segstart[B] = N sentinel
__global__ void segstart_kernel(const void* __restrict__ braw, int n) {
    int i = blockIdx.x * blockDim.x + threadIdx.x;
    if (i > n) return;
    int cur  = (i == n) ? NNB : seg_of(braw, i);
    if (cur > NNB) cur = NNB;
    int prev = (i == 0) ? -1 : seg_of(braw, i - 1);
    for (int b = prev + 1; b <= cur; b++) g_segstart[b] = i;
}

// ---------------- step 0 LSTM: q_star = 0, h = 0 -> gates = bias only ----------------
// h0 and c0 are per-column constants, broadcast across all b rows. dst = g_bufB.
__global__ void __launch_bounds__(256) bias0_kernel() {
    int c = threadIdx.x;
    int b = blockIdx.x;
    float4 bs = *(const float4*)&g_bias[c * 4];
    float si = 1.f / (1.f + __expf(-bs.x));
    float so = 1.f / (1.f + __expf(-bs.w));
    float tg = tanhf(bs.z);
    float c0 = si * tg;                       // c_prev = 0 -> forget term vanishes
    float h0 = so * tanhf(c0);
    g_c[b * 256 + c] = c0;
    g_bufB[b * 512 + c] = h0;
}

// ---------------- fused LSTM: GEMM [512x1024x512] + gate activations ----------------
// A = prev q_star [512][512]. B = g_Wf rows gathered via the n'->no permutation
// (n' = c*4+g  <->  no = g*256+c), so each thread's 4 N-accumulators are the
// (i,f,g,o) gates of one (b,c) cell. 64x64 tile, 256 threads, 4x4/thread,
// double-buffered smem with register-staged prefetch.
// dstB: 1 -> src g_bufA, dst g_bufB; 0 -> src g_bufB, dst g_bufA.
__global__ void __launch_bounds__(256, 1) gemm_lstm_kernel(int dstB, float* __restrict__ out2)
{
    const float* A  = dstB ? g_bufA : g_bufB;
    float* hout     = dstB ? g_bufB : g_bufA;

    __shared__ float sA[2][16][68];   // [buf][k][m]
    __shared__ float sB[2][16][68];   // [buf][k][n']

    int tid = threadIdx.x;
    int tm = tid & 15;                // m sub-tile (4 rows)
    int tn = tid >> 4;                // n' sub-tile (4 cols = gates of one c)
    int m0 = blockIdx.y * 64;
    int n0 = blockIdx.x * 64;

    // staging roles (symmetric for A and B): row = tid>>2, k-quad = tid&3
    int srow = tid >> 2;              // 0..63
    int skq  = tid & 3;               // 0..3
    const float* aptr = A + (m0 + srow) * 512 + skq * 4;
    int np = n0 + srow;
    int no = (np & 3) * 256 + (np >> 2);            // row permutation
    const float* bptr = g_Wf + no * 512 + skq * 4;

    float4 ra = *(const float4*)aptr;
    float4 rb = *(const float4*)bptr;
    sA[0][skq * 4 + 0][srow] = ra.x;
    sA[0][skq * 4 + 1][srow] = ra.y;
    sA[0][skq * 4 + 2][srow] = ra.z;
    sA[0][skq * 4 + 3][srow] = ra.w;
    sB[0][skq * 4 + 0][srow] = rb.x;
    sB[0][skq * 4 + 1][srow] = rb.y;
    sB[0][skq * 4 + 2][srow] = rb.z;
    sB[0][skq * 4 + 3][srow] = rb.w;
    __syncthreads();

    float acc[4][4];
    #pragma unroll
    for (int r = 0; r < 4; r++)
        #pragma unroll
        for (int n = 0; n < 4; n++) acc[r][n] = 0.f;

    const int NK = 512 / 16;
    for (int kb = 0; kb < NK; kb++) {
        int cur = kb & 1;
        if (kb + 1 < NK) {
            ra = *(const float4*)(aptr + (kb + 1) * 16);
            rb = *(const float4*)(bptr + (kb + 1) * 16);
        }
        #pragma unroll
        for (int kk = 0; kk < 16; kk++) {
            float4 va = *(float4*)&sA[cur][kk][tm * 4];
            float4 vb = *(float4*)&sB[cur][kk][tn * 4];
            acc[0][0] += va.x * vb.x; acc[0][1] += va.x * vb.y; acc[0][2] += va.x * vb.z; acc[0][3] += va.x * vb.w;
            acc[1][0] += va.y * vb.x; acc[1][1] += va.y * vb.y; acc[1][2] += va.y * vb.z; acc[1][3] += va.y * vb.w;
            acc[2][0] += va.z * vb.x; acc[2][1] += va.z * vb.y; acc[2][2] += va.z * vb.z; acc[2][3] += va.z * vb.w;
            acc[3][0] += va.w * vb.x; acc[3][1] += va.w * vb.y; acc[3][2] += va.w * vb.z; acc[3][3] += va.w * vb.w;
        }
        if (kb + 1 < NK) {
            int nxt = cur ^ 1;
            sA[nxt][skq * 4 + 0][srow] = ra.x;
            sA[nxt][skq * 4 + 1][srow] = ra.y;
            sA[nxt][skq * 4 + 2][srow] = ra.z;
            sA[nxt][skq * 4 + 3][srow] = ra.w;
            sB[nxt][skq * 4 + 0][srow] = rb.x;
            sB[nxt][skq * 4 + 1][srow] = rb.y;
            sB[nxt][skq * 4 + 2][srow] = rb.z;
            sB[nxt][skq * 4 + 3][srow] = rb.w;
        }
        __syncthreads();
    }

    // fused LSTM pointwise epilogue: thread owns gates (i,f,g,o) of 4 (b,c) cells
    int c = (n0 >> 2) + tn;
    float4 bs = *(const float4*)&g_bias[n0 + tn * 4];
    #pragma unroll
    for (int mi = 0; mi < 4; mi++) {
        int b = m0 + tm * 4 + mi;
        float gi = acc[mi][0] + bs.x;
        float gf = acc[mi][1] + bs.y;
        float gg = acc[mi][2] + bs.z;
        float go = acc[mi][3] + bs.w;
        float si = 1.f / (1.f + __expf(-gi));
        float sf = 1.f / (1.f + __expf(-gf));
        float so = 1.f / (1.f + __expf(-go));
        float tg = tanhf(gg);
        float cn = sf * g_c[b * 256 + c] + si * tg;   // each (b,c) owned by one thread
        float hn = so * tanhf(cn);
        g_c[b * 256 + c] = cn;
        hout[b * 512 + c] = hn;
        if (out2) out2[b * 512 + c] = hn;
    }
}

// ---------------- fused segment-softmax attention (single pass over x) ----------------
// One block per graph. 16 warps stride the segment; lane owns 8 columns.
// Online softmax: each x row is read ONCE for both the logit and the weighted sum.
// dstB: which buffer holds this step's q (and receives r).
__global__ void __launch_bounds__(512) attn_kernel(
    const float* __restrict__ x, int dstB, float* __restrict__ out2)
{
    float* buf = dstB ? g_bufB : g_bufA;

    int b = blockIdx.x;
    int s = g_segstart[b];
    int e = g_segstart[b + 1];
    int tid  = threadIdx.x;
    int lane = tid & 31;
    int w    = tid >> 5;

    __shared__ float sm_m[16];
    __shared__ float sm_Z[16];
    __shared__ float sm_acc[16 * 256];

    const float4* qp = (const float4*)(buf + b * 512 + lane * 8);
    float4 q0 = __ldg(qp);
    float4 q1 = __ldg(qp + 1);

    float m = -1e30f, Z = 0.f;
    float a0 = 0.f, a1 = 0.f, a2 = 0.f, a3 = 0.f, a4 = 0.f, a5 = 0.f, a6 = 0.f, a7 = 0.f;

    int i = s + w;
    float4 cx0 = make_float4(0.f, 0.f, 0.f, 0.f), cx1 = cx0, nx0 = cx0, nx1 = cx0;
    if (i < e) {
        const float4* p = (const float4*)(x + (size_t)i * 256 + lane * 8);
        cx0 = __ldg(p); cx1 = __ldg(p + 1);
    }
    while (i < e) {
        int inext = i + 16;
        if (inext < e) {
            const float4* p = (const float4*)(x + (size_t)inext * 256 + lane * 8);
            nx0 = __ldg(p); nx1 = __ldg(p + 1);
        }
        float d = cx0.x * q0.x + cx0.y * q0.y + cx0.z * q0.z + cx0.w * q0.w
                + cx1.x * q1.x + cx1.y * q1.y + cx1.z * q1.z + cx1.w * q1.w;
        #pragma unroll
        for (int o = 16; o > 0; o >>= 1) d += __shfl_xor_sync(0xffffffffu, d, o);

        float mn = fmaxf(m, d);
        float sc = __expf(m - mn);     // first iteration: underflows to 0
        float p  = __expf(d - mn);
        Z = Z * sc + p;
        a0 = a0 * sc + p * cx0.x;
        a1 = a1 * sc + p * cx0.y;
        a2 = a2 * sc + p * cx0.z;
        a3 = a3 * sc + p * cx0.w;
        a4 = a4 * sc + p * cx1.x;
        a5 = a5 * sc + p * cx1.y;
        a6 = a6 * sc + p * cx1.z;
        a7 = a7 * sc + p * cx1.w;
        m = mn;

        cx0 = nx0; cx1 = nx1;
        i = inext;
    }

    float4* ap = (float4*)&sm_acc[w * 256 + lane * 8];
    ap[0] = make_float4(a0, a1, a2, a3);
    ap[1] = make_float4(a4, a5, a6, a7);
    if (lane == 0) { sm_m[w] = m; sm_Z[w] = Z; }
    __syncthreads();

    if (tid < 256) {
        float M = -1e30f;
        #pragma unroll
        for (int ww = 0; ww < 16; ww++) M = fmaxf(M, sm_m[ww]);
        float r = 0.f;
        if (M > -1e29f) {
            float Zt = 0.f;
            #pragma unroll
            for (int ww = 0; ww < 16; ww++) {
                float sc = __expf(sm_m[ww] - M);
                Zt += sc * sm_Z[ww];
                r  += sc * sm_acc[ww * 256 + tid];
            }
            r = r / Zt;
        }
        buf[b * 512 + 256 + tid] = r;
        if (out2) out2[b * 512 + 256 + tid] = r;
    }
}

// ---------------- launcher: pure kernel launches, nothing else ----------------
extern "C" void kernel_launch(void* const* d_in, const int* in_sizes, int n_in,
                              void* d_out, int out_size) {
    const float* x     = (const float*)d_in[0];
    const void*  batch = d_in[1];
    const float* W_ih  = (const float*)d_in[2];
    const float* W_hh  = (const float*)d_in[3];
    const float* b_ih  = (const float*)d_in[4];
    const float* b_hh  = (const float*)d_in[5];
    int n = in_sizes[1];

    setup_kernel<<<(1024 * 512 + 255) / 256, 256>>>(W_ih, W_hh, b_ih, b_hh);
    detect_kernel<<<128, 256>>>((const unsigned int*)batch, n);
    segstart_kernel<<<(n + 256) / 256, 256>>>(batch, n);

    // step 0: LSTM degenerates to bias-only broadcast into g_bufB
    bias0_kernel<<<NNB, 256>>>();
    attn_kernel<<<NNB, 512>>>(x, /*dstB=*/1, nullptr);

    // step 1: B -> A ; step 2: A -> B (writes d_out)
    dim3 ggrid(16, 8);   // (n' tiles, m tiles)
    gemm_lstm_kernel<<<ggrid, 256>>>(/*dstB=*/0, nullptr);
    attn_kernel<<<NNB, 512>>>(x, /*dstB=*/0, nullptr);

    gemm_lstm_kernel<<<ggrid, 256>>>(/*dstB=*/1, (float*)d_out);
    attn_kernel<<<NNB, 512>>>(x, /*dstB=*/1, (float*)d_out);
}